// round 14
// baseline (speedup 1.0000x reference)
#include <cuda_runtime.h>
#include <cuda_fp16.h>
#include <cstdint>

// ---------------- problem constants ----------------
constexpr int NN   = 100000;
constexpr int SAMP = 2;
constexpr int GG   = 8;
constexpr int EE   = 400000;
constexpr int MIDC = 256;
constexpr int NL   = 4;
constexpr int MROWS = SAMP * NN;       // 200000
constexpr int MPAD  = 200192;          // 782 * 256
constexpr int MT256 = MPAD / 256;      // 782
constexpr int NBPAD = 100096;          // 391 * 256
constexpr int MTB   = NBPAD / 256;     // 391
constexpr int KB    = 224;             // base K (7 chunks of 32; 223 real)
constexpr int KS    = 64;              // sample K (2 chunks; 42 real)

// ---------------- static scratch ----------------
__device__ __half g_xinb[(size_t)NBPAD * KB];
__device__ __half g_xins[(size_t)MPAD * KS];
__device__ __half g_y0 [(size_t)NBPAD * MIDC];
__device__ __half g_xa [(size_t)MPAD * MIDC];
__device__ __half g_xb [(size_t)MPAD * MIDC];
__device__ __half g_P  [(size_t)MPAD * 512];
__device__ __half g_wbase[256 * KB];             // [n256][k224] fp16
__device__ __half g_wsamp[256 * KS];             // [n256][k64]  fp16
__device__ __half g_wlay[NL * 512 * 256];        // [l][n512][k256] fp16
__device__ int   g_cntf[NN], g_cntr[NN];
__device__ int   g_offf[NN + 1], g_offr[NN + 1];
__device__ int   g_curf[NN], g_curr[NN];
__device__ int   g_csrf[EE], g_csrr[EE];
__device__ float g_invf[NN], g_invr[NN];

// ---------------- PTX helpers ----------------
__device__ __forceinline__ uint32_t smem_u32(const void* p) {
    uint32_t a;
    asm("{ .reg .u64 t; cvta.to.shared.u64 t, %1; cvt.u32.u64 %0, t; }" : "=r"(a) : "l"(p));
    return a;
}
__device__ __forceinline__ void cp16(uint32_t dst, const void* src) {
    asm volatile("cp.async.ca.shared.global [%0], [%1], 16;" :: "r"(dst), "l"(src));
}
__device__ __forceinline__ void cp_commit() { asm volatile("cp.async.commit_group;"); }
__device__ __forceinline__ void cp_wait1()  { asm volatile("cp.async.wait_group 1;"); }
__device__ __forceinline__ void cp_wait0()  { asm volatile("cp.async.wait_group 0;"); }
__device__ __forceinline__ void ldsm4(uint32_t* r, uint32_t a) {
    asm volatile("ldmatrix.sync.aligned.m8n8.x4.shared.b16 {%0,%1,%2,%3}, [%4];"
                 : "=r"(r[0]), "=r"(r[1]), "=r"(r[2]), "=r"(r[3]) : "r"(a));
}
__device__ __forceinline__ void mma16816(float* d, const uint32_t* a, const uint32_t* b) {
    asm volatile("mma.sync.aligned.m16n8k16.row.col.f32.f16.f16.f32 "
                 "{%0,%1,%2,%3}, {%4,%5,%6,%7}, {%8,%9}, {%0,%1,%2,%3};"
                 : "+f"(d[0]), "+f"(d[1]), "+f"(d[2]), "+f"(d[3])
                 : "r"(a[0]), "r"(a[1]), "r"(a[2]), "r"(a[3]), "r"(b[0]), "r"(b[1]));
}

// ---------------- graph structure ----------------
__global__ void hist_kernel(const int* __restrict__ src, const int* __restrict__ tgt) {
    int e = blockIdx.x * blockDim.x + threadIdx.x;
    if (e >= EE) return;
    atomicAdd(&g_cntf[tgt[e]], 1);
    atomicAdd(&g_cntr[src[e]], 1);
}

__global__ void scan_kernel() {
    const int* cnt = blockIdx.x ? g_cntr : g_cntf;
    int* off       = blockIdx.x ? g_offr : g_offf;
    float* inv     = blockIdx.x ? g_invr : g_invf;
    int* cur       = blockIdx.x ? g_curr : g_curf;
    __shared__ int wsum[32];
    __shared__ int chunk_total;
    __shared__ int carry;
    int tid = threadIdx.x, lane = tid & 31, wid = tid >> 5;
    if (tid == 0) carry = 0;
    __syncthreads();
    for (int base = 0; base < NN; base += 1024) {
        int i = base + tid;
        int v = (i < NN) ? cnt[i] : 0;
        int x = v;
        #pragma unroll
        for (int d = 1; d < 32; d <<= 1) {
            int t = __shfl_up_sync(0xffffffffu, x, d);
            if (lane >= d) x += t;
        }
        if (lane == 31) wsum[wid] = x;
        __syncthreads();
        if (wid == 0) {
            int wv = wsum[lane];
            int y = wv;
            #pragma unroll
            for (int d = 1; d < 32; d <<= 1) {
                int t = __shfl_up_sync(0xffffffffu, y, d);
                if (lane >= d) y += t;
            }
            if (lane == 31) chunk_total = y;
            wsum[lane] = y - wv;
        }
        __syncthreads();
        if (i < NN) off[i] = carry + wsum[wid] + (x - v);
        __syncthreads();
        if (tid == 0) carry += chunk_total;
        __syncthreads();
    }
    if (threadIdx.x == 0) off[NN] = carry;
    __syncthreads();
    // fused inv-degree + cursor init
    for (int i = tid; i < NN; i += 1024) {
        inv[i] = 1.f / fmaxf((float)cnt[i], 1.f);
        cur[i] = off[i];
    }
}

__global__ void fill_kernel(const int* __restrict__ src, const int* __restrict__ tgt) {
    int e = blockIdx.x * blockDim.x + threadIdx.x;
    if (e >= EE) return;
    int s = src[e], t = tgt[e];
    g_csrf[atomicAdd(&g_curf[t], 1)] = s;
    g_csrr[atomicAdd(&g_curr[s], 1)] = t;
}

// ---------------- merged weight prep (single fp16 plane) ----------------
__global__ void prep_w(const float* __restrict__ preW,
                       const float* __restrict__ cwl, const float* __restrict__ cwr,
                       const float* __restrict__ rwl, const float* __restrict__ rwr) {
    int idx = blockIdx.x * blockDim.x + threadIdx.x;
    if (idx < 256 * KB) {
        int n = idx / KB, k = idx % KB;
        float v = (k < 223) ? preW[(size_t)k * 256 + n] : 0.f;
        g_wbase[idx] = __float2half_rn(v);
        return;
    }
    idx -= 256 * KB;
    if (idx < 256 * KS) {
        int n = idx / KS, k = idx % KS;
        float v = (k < 42) ? preW[(size_t)(223 + k) * 256 + n] : 0.f;
        g_wsamp[idx] = __float2half_rn(v);
        return;
    }
    int j = idx - 256 * KS;
    if (j >= NL * 512 * 256) return;
    int l = j >> 17;
    int r2 = j & 131071;
    int n = r2 >> 8, k = r2 & 255;
    int mat = n >> 7, o = n & 127;
    const float* s = (mat == 0) ? cwl : (mat == 1) ? cwr : (mat == 2) ? rwl : rwr;
    float v = s[(size_t)l * 32768 + k * 128 + o];
    g_wlay[(size_t)l * (512 * 256) + (size_t)n * 256 + k] = __float2half_rn(v);
}

// ---------------- merged input assembly ----------------
__global__ void assemble_kernel(const float* __restrict__ xf, const float* __restrict__ dimf,
                                const float* __restrict__ layf, const float* __restrict__ tilef,
                                const float* __restrict__ emb, const int* __restrict__ opc,
                                const int* __restrict__ batch) {
    size_t idx = (size_t)blockIdx.x * blockDim.x + threadIdx.x;
    const size_t baseTot = (size_t)NBPAD * KB;
    if (idx < baseTot) {
        int c = (int)(idx % KB);
        int n = (int)(idx / KB);
        float v = 0.f;
        if (n < NN) {
            if (c < 53)       v = xf[(size_t)n * 53 + c];
            else if (c < 85)  v = emb[(size_t)opc[n] * 32 + (c - 53)];
            else if (c < 223) v = dimf[(size_t)n * 138 + (c - 85)];
        }
        g_xinb[idx] = __float2half_rn(v);
        return;
    }
    idx -= baseTot;
    if (idx >= (size_t)MPAD * KS) return;
    int c = (int)(idx % KS);
    int m = (int)(idx / KS);
    float v = 0.f;
    if (m < MROWS) {
        int s = m / NN, n = m % NN;
        if (c < 24)      v = layf[((size_t)n * SAMP + s) * 24 + c];
        else if (c < 42) v = tilef[((size_t)batch[n] * SAMP + s) * 18 + (c - 24)];
    }
    g_xins[idx] = __float2half_rn(v);
}

// ---------------- fp16 single-pass streaming GEMM, CTA 256x64, warp 64x32 ----------------
constexpr int STAGE = 25600;
constexpr int NSTG  = 3;
constexpr int GEMM_SMEM = NSTG * STAGE;   // 76800

__global__ __launch_bounds__(256, 2) void gemm_mma(
    const __half* __restrict__ A, int lda, int kchunks,
    const __half* __restrict__ W, int kw,
    const float* __restrict__ bias, const __half* __restrict__ Y0, int mode,
    __half* __restrict__ O, int ldc) {
    extern __shared__ char smem[];
    uint32_t sb = smem_u32(smem);
    const int tid = threadIdx.x;
    const int lane = tid & 31, wid = tid >> 5;
    const int wm = wid >> 1, wn = wid & 1;
    const size_t m0 = (size_t)blockIdx.y * 256;
    const int n0 = blockIdx.x * 64;

    const __half* srcb[5];
    uint32_t dsto[5];
    #pragma unroll
    for (int i = 0; i < 5; i++) {
        if (i < 4) {
            int u = tid + i * 256;
            int row = u >> 2, seg = u & 3;
            srcb[i] = A + (m0 + row) * (size_t)lda + seg * 8;
            dsto[i] = (uint32_t)(row * 80 + seg * 16);
        } else {
            int col = tid >> 2, sg = tid & 3;
            srcb[i] = W + (size_t)(n0 + col) * kw + sg * 8;
            dsto[i] = (uint32_t)(20480 + col * 80 + sg * 16);
        }
    }

    float acc[4][4][4];
    #pragma unroll
    for (int i = 0; i < 4; i++)
        #pragma unroll
        for (int j = 0; j < 4; j++)
            #pragma unroll
            for (int q = 0; q < 4; q++) acc[i][j][q] = 0.f;

    #pragma unroll
    for (int i = 0; i < 5; i++) cp16(sb + dsto[i], srcb[i]);
    cp_commit();
    if (kchunks > 1) {
        #pragma unroll
        for (int i = 0; i < 5; i++) cp16(sb + STAGE + dsto[i], srcb[i] + 32);
        cp_commit();
    }
    cp_wait1();
    __syncthreads();

    const int sub = lane >> 3, rr = lane & 7;
    const int ro = (sub & 1) * 8 + rr;
    const int co = ((sub >> 1) & 1) * 8;

    for (int ch = 0; ch < kchunks; ch++) {
        if (ch + 2 < kchunks) {
            uint32_t db = sb + ((ch + 2) % NSTG) * STAGE;
            int koff = (ch + 2) * 32;
            #pragma unroll
            for (int i = 0; i < 5; i++) cp16(db + dsto[i], srcb[i] + koff);
            cp_commit();
        }
        uint32_t base = sb + (ch % NSTG) * STAGE;
        #pragma unroll
        for (int kk = 0; kk < 32; kk += 16) {
            uint32_t af[4][4];
            #pragma unroll
            for (int mi = 0; mi < 4; mi++)
                ldsm4(af[mi], base + (uint32_t)((wm * 64 + mi * 16 + ro) * 80 + (kk + co) * 2));
            uint32_t bfr[4][2];
            #pragma unroll
            for (int j2 = 0; j2 < 2; j2++) {
                uint32_t t4[4];
                ldsm4(t4, base + 20480 +
                      (uint32_t)((wn * 32 + j2 * 16 + ro) * 80 + (kk + co) * 2));
                bfr[2 * j2][0] = t4[0]; bfr[2 * j2][1] = t4[2];
                bfr[2 * j2 + 1][0] = t4[1]; bfr[2 * j2 + 1][1] = t4[3];
            }
            #pragma unroll
            for (int mi = 0; mi < 4; mi++)
                #pragma unroll
                for (int nj = 0; nj < 4; nj++)
                    mma16816(acc[mi][nj], af[mi], bfr[nj]);
        }
        if (ch + 1 < kchunks) {
            if (ch + 2 < kchunks) cp_wait1(); else cp_wait0();
            __syncthreads();
        }
    }

    const int g = lane >> 2, t4i = lane & 3;
    #pragma unroll
    for (int mi = 0; mi < 4; mi++) {
        #pragma unroll
        for (int nj = 0; nj < 4; nj++) {
            size_t row = m0 + wm * 64 + mi * 16 + g;
            int col = n0 + wn * 32 + nj * 8 + t4i * 2;
            float2 v0 = make_float2(acc[mi][nj][0], acc[mi][nj][1]);
            float2 v1 = make_float2(acc[mi][nj][2], acc[mi][nj][3]);
            if (mode == 1) {
                size_t nd0 = row < (size_t)NN ? row : (row < (size_t)MROWS ? row - NN : 0);
                size_t row8 = row + 8;
                size_t nd1 = row8 < (size_t)NN ? row8 : (row8 < (size_t)MROWS ? row8 - NN : 0);
                float2 y0 = __half22float2(*reinterpret_cast<const __half2*>(Y0 + nd0 * 256 + col));
                float2 y1 = __half22float2(*reinterpret_cast<const __half2*>(Y0 + nd1 * 256 + col));
                float b0v = bias[col], b1v = bias[col + 1];
                v0.x = fmaxf(v0.x + y0.x + b0v, 0.f); v0.y = fmaxf(v0.y + y0.y + b1v, 0.f);
                v1.x = fmaxf(v1.x + y1.x + b0v, 0.f); v1.y = fmaxf(v1.y + y1.y + b1v, 0.f);
            }
            *reinterpret_cast<__half2*>(O + row * ldc + col) = __float22half2_rn(v0);
            *reinterpret_cast<__half2*>(O + (row + 8) * ldc + col) = __float22half2_rn(v1);
        }
    }
}

// ---------------- fused gather + epilogue + optional head ----------------
__device__ __forceinline__ void acc4h(float* a, uint2 u) {
    float2 f0 = __half22float2(*reinterpret_cast<const __half2*>(&u.x));
    float2 f1 = __half22float2(*reinterpret_cast<const __half2*>(&u.y));
    a[0] += f0.x; a[1] += f0.y; a[2] += f1.x; a[3] += f1.y;
}
__device__ __forceinline__ void store4_h(__half* X, size_t off, const float* v) {
    __half2 p0 = __float22half2_rn(make_float2(v[0], v[1]));
    __half2 p1 = __float22half2_rn(make_float2(v[2], v[3]));
    uint2 u;
    u.x = *reinterpret_cast<uint32_t*>(&p0);
    u.y = *reinterpret_cast<uint32_t*>(&p1);
    *reinterpret_cast<uint2*>(X + off) = u;
}

// grid must be exactly NN*32/256 blocks (NN divisible) so no warp early-exits.
__global__ void gather_ep(const __half* __restrict__ P,
                          const float* __restrict__ bconv, const float* __restrict__ brev,
                          __half* __restrict__ X,
                          const float* __restrict__ hw,   // headW slice or nullptr
                          const int* __restrict__ batchv, float* __restrict__ out) {
    __shared__ float part[GG * SAMP];
    int tid = threadIdx.x;
    if (hw) {
        if (tid < GG * SAMP) part[tid] = 0.f;
        __syncthreads();
    }
    int w = (blockIdx.x * blockDim.x + tid) >> 5;
    int lane = tid & 31;
    int c4 = lane * 4;
    float aF0[4] = {0, 0, 0, 0}, aF1[4] = {0, 0, 0, 0};
    float aR0[4] = {0, 0, 0, 0}, aR1[4] = {0, 0, 0, 0};
    int b0 = g_offf[w], b1 = g_offf[w + 1];
    for (int j = b0; j < b1; j++) {
        int nb = g_csrf[j];
        acc4h(aF0, *reinterpret_cast<const uint2*>(P + (size_t)nb * 512 + c4));
        acc4h(aF1, *reinterpret_cast<const uint2*>(P + (size_t)(NN + nb) * 512 + c4));
    }
    b0 = g_offr[w]; b1 = g_offr[w + 1];
    for (int j = b0; j < b1; j++) {
        int nb = g_csrr[j];
        acc4h(aR0, *reinterpret_cast<const uint2*>(P + (size_t)nb * 512 + 256 + c4));
        acc4h(aR1, *reinterpret_cast<const uint2*>(P + (size_t)(NN + nb) * 512 + 256 + c4));
    }
    float ivf = g_invf[w], ivr = g_invr[w];
    float4 bc = *reinterpret_cast<const float4*>(bconv + c4);
    float4 br = *reinterpret_cast<const float4*>(brev + c4);
    const float* bcp = &bc.x;
    const float* brp = &br.x;
    float hwc[4], hwr[4];
    if (hw) {
        #pragma unroll
        for (int q = 0; q < 4; q++) {
            hwc[q] = hw[c4 + q];
            hwr[q] = hw[128 + c4 + q];
        }
    }
    float dot[SAMP] = {0.f, 0.f};
    #pragma unroll
    for (int s = 0; s < SAMP; s++) {
        size_t rowm = (size_t)s * NN + w;
        const float* aF = s ? aF1 : aF0;
        const float* aR = s ? aR1 : aR0;
        float rf[4] = {0, 0, 0, 0}, rr2[4] = {0, 0, 0, 0};
        acc4h(rf,  *reinterpret_cast<const uint2*>(P + rowm * 512 + 128 + c4));
        acc4h(rr2, *reinterpret_cast<const uint2*>(P + rowm * 512 + 384 + c4));
        float oF[4], oR[4];
        #pragma unroll
        for (int q = 0; q < 4; q++) {
            oF[q] = fmaxf(aF[q] * ivf + rf[q]  + bcp[q], 0.f);
            oR[q] = fmaxf(aR[q] * ivr + rr2[q] + brp[q], 0.f);
        }
        if (X) {
            store4_h(X, rowm * MIDC + c4, oF);
            store4_h(X, rowm * MIDC + 128 + c4, oR);
        }
        if (hw) {
            float d = 0.f;
            #pragma unroll
            for (int q = 0; q < 4; q++) d += oF[q] * hwc[q] + oR[q] * hwr[q];
            dot[s] = d;
        }
    }
    if (hw) {
        #pragma unroll
        for (int s = 0; s < SAMP; s++)
            #pragma unroll
            for (int d = 16; d > 0; d >>= 1)
                dot[s] += __shfl_down_sync(0xffffffffu, dot[s], d);
        if (lane == 0) {
            int g = batchv[w];
            atomicAdd(&part[g * SAMP + 0], dot[0]);
            atomicAdd(&part[g * SAMP + 1], dot[1]);
        }
        __syncthreads();
        if (tid < GG * SAMP && part[tid] != 0.f) atomicAdd(&out[tid], part[tid]);
    }
}

// ---------------- output init ----------------
__global__ void init_out_kernel(float* out, const float* __restrict__ hb) {
    int i = threadIdx.x;
    if (i < GG * SAMP) out[i] = hb[0];
}

// ---------------- launch ----------------
extern "C" void kernel_launch(void* const* d_in, const int* in_sizes, int n_in,
                              void* d_out, int out_size) {
    const float* x_feat    = (const float*)d_in[0];
    const float* dim_feat  = (const float*)d_in[1];
    const float* lay_feat  = (const float*)d_in[2];
    const float* tile_feat = (const float*)d_in[3];
    const float* emb       = (const float*)d_in[4];
    const float* preW      = (const float*)d_in[5];
    const float* preb      = (const float*)d_in[6];
    const float* convWl    = (const float*)d_in[7];
    const float* convWr    = (const float*)d_in[8];
    const float* convb     = (const float*)d_in[9];
    const float* revWl     = (const float*)d_in[10];
    const float* revWr     = (const float*)d_in[11];
    const float* revb      = (const float*)d_in[12];
    const float* headW     = (const float*)d_in[13];
    const float* headb     = (const float*)d_in[14];
    const int*   opcode    = (const int*)d_in[15];
    const int*   batch     = (const int*)d_in[16];
    const int*   eidx      = (const int*)d_in[17];
    const int* src = eidx;
    const int* tgt = eidx + EE;
    float* out = (float*)d_out;

    int *cntf, *cntr;
    __half *xinb, *xins, *y0, *xa, *xb, *P, *wbase, *wsamp, *wlay;
    cudaGetSymbolAddress((void**)&cntf, g_cntf);
    cudaGetSymbolAddress((void**)&cntr, g_cntr);
    cudaGetSymbolAddress((void**)&xinb, g_xinb);
    cudaGetSymbolAddress((void**)&xins, g_xins);
    cudaGetSymbolAddress((void**)&y0, g_y0);
    cudaGetSymbolAddress((void**)&xa, g_xa);
    cudaGetSymbolAddress((void**)&xb, g_xb);
    cudaGetSymbolAddress((void**)&P, g_P);
    cudaGetSymbolAddress((void**)&wbase, g_wbase);
    cudaGetSymbolAddress((void**)&wsamp, g_wsamp);
    cudaGetSymbolAddress((void**)&wlay, g_wlay);

    static bool attr_done = false;
    if (!attr_done) {
        cudaFuncSetAttribute(gemm_mma, cudaFuncAttributeMaxDynamicSharedMemorySize, GEMM_SMEM);
        attr_done = true;
    }

    cudaMemsetAsync(cntf, 0, NN * sizeof(int), 0);                                    // 1
    cudaMemsetAsync(cntr, 0, NN * sizeof(int), 0);                                    // 2
    {
        int tot = 256 * KB + 256 * KS + NL * 512 * 256;
        prep_w<<<(tot + 255) / 256, 256>>>(preW, convWl, convWr, revWl, revWr);       // 3
    }
    {
        size_t tot = (size_t)NBPAD * KB + (size_t)MPAD * KS;
        assemble_kernel<<<(unsigned)((tot + 255) / 256), 256>>>(                      // 4
            x_feat, dim_feat, lay_feat, tile_feat, emb, opcode, batch);
    }
    {
        dim3 grid(4, MTB);                                                            // 5: base GEMM
        gemm_mma<<<grid, 256, GEMM_SMEM>>>(xinb, KB, KB / 32, wbase, KB,
                                           nullptr, nullptr, 0, y0, 256);
    }
    {
        dim3 grid(4, MT256);                                                          // 6: sample GEMM (ncu slot)
        gemm_mma<<<grid, 256, GEMM_SMEM>>>(xins, KS, KS / 32, wsamp, KS,
                                           preb, y0, 1, xa, 256);
    }
    // graph structure (needed before first gather)
    hist_kernel<<<(EE + 255) / 256, 256>>>(src, tgt);
    scan_kernel<<<2, 1024>>>();
    fill_kernel<<<(EE + 255) / 256, 256>>>(src, tgt);
    init_out_kernel<<<1, 32>>>(out, headb);

    __half *cur = xa, *nxt = xb;
    for (int i = 0; i < NL; i++) {
        dim3 grid(8, MT256);
        gemm_mma<<<grid, 256, GEMM_SMEM>>>(cur, 256, 8,
                                           wlay + (size_t)i * (512 * 256), 256,
                                           nullptr, nullptr, 0, P, 512);
        const float* hw = (i == 2) ? headW : (i == 3) ? headW + 256 : nullptr;
        __half* Xo = (i == 3) ? nullptr : nxt;
        gather_ep<<<NN * 32 / 256, 256>>>(P, convb + i * 128, revb + i * 128,
                                          Xo, hw, batch, out);
        __half* t = cur; cur = nxt; nxt = t;
    }
}

// round 16
// speedup vs baseline: 1.0406x; 1.0406x over previous
#include <cuda_runtime.h>
#include <cuda_fp16.h>
#include <cstdint>

// ---------------- problem constants ----------------
constexpr int NN   = 100000;
constexpr int SAMP = 2;
constexpr int GG   = 8;
constexpr int EE   = 400000;
constexpr int MIDC = 256;
constexpr int NL   = 4;
constexpr int MROWS = SAMP * NN;       // 200000
constexpr int MPAD  = 200192;          // 782 * 256
constexpr int MT256 = MPAD / 256;      // 782
constexpr int NBPAD = 100096;          // 391 * 256
constexpr int MTB   = NBPAD / 256;     // 391
constexpr int KB    = 224;             // base K (7 chunks of 32; 223 real)
constexpr int KS    = 64;              // sample K (2 chunks; 42 real)

// ---------------- static scratch ----------------
__device__ __half g_xinb[(size_t)NBPAD * KB];
__device__ __half g_xins[(size_t)MPAD * KS];
__device__ __half g_y0 [(size_t)NBPAD * MIDC];
__device__ __half g_xa [(size_t)MPAD * MIDC];
__device__ __half g_xb [(size_t)MPAD * MIDC];
__device__ __half g_P  [(size_t)MPAD * 512];
__device__ __half g_wbase[256 * KB];             // [n256][k224] fp16
__device__ __half g_wsamp[256 * KS];             // [n256][k64]  fp16
__device__ __half g_wlay[NL * 512 * 256];        // [l][n512][k256] fp16
__device__ int   g_cntf[NN], g_cntr[NN];
__device__ int   g_offf[NN + 1], g_offr[NN + 1];
__device__ int   g_curf[NN], g_curr[NN];
__device__ int   g_csrf[EE], g_csrr[EE];
__device__ float g_invf[NN], g_invr[NN];

// ---------------- PTX helpers ----------------
__device__ __forceinline__ uint32_t smem_u32(const void* p) {
    uint32_t a;
    asm("{ .reg .u64 t; cvta.to.shared.u64 t, %1; cvt.u32.u64 %0, t; }" : "=r"(a) : "l"(p));
    return a;
}
__device__ __forceinline__ void cp16(uint32_t dst, const void* src) {
    asm volatile("cp.async.ca.shared.global [%0], [%1], 16;" :: "r"(dst), "l"(src));
}
__device__ __forceinline__ void cp_commit() { asm volatile("cp.async.commit_group;"); }
__device__ __forceinline__ void cp_wait1()  { asm volatile("cp.async.wait_group 1;"); }
__device__ __forceinline__ void cp_wait0()  { asm volatile("cp.async.wait_group 0;"); }
__device__ __forceinline__ void ldsm4(uint32_t* r, uint32_t a) {
    asm volatile("ldmatrix.sync.aligned.m8n8.x4.shared.b16 {%0,%1,%2,%3}, [%4];"
                 : "=r"(r[0]), "=r"(r[1]), "=r"(r[2]), "=r"(r[3]) : "r"(a));
}
__device__ __forceinline__ void mma16816(float* d, const uint32_t* a, const uint32_t* b) {
    asm volatile("mma.sync.aligned.m16n8k16.row.col.f32.f16.f16.f32 "
                 "{%0,%1,%2,%3}, {%4,%5,%6,%7}, {%8,%9}, {%0,%1,%2,%3};"
                 : "+f"(d[0]), "+f"(d[1]), "+f"(d[2]), "+f"(d[3])
                 : "r"(a[0]), "r"(a[1]), "r"(a[2]), "r"(a[3]), "r"(b[0]), "r"(b[1]));
}

// ---------------- graph structure ----------------
__global__ void hist_kernel(const int* __restrict__ src, const int* __restrict__ tgt) {
    int e = blockIdx.x * blockDim.x + threadIdx.x;
    if (e >= EE) return;
    atomicAdd(&g_cntf[tgt[e]], 1);
    atomicAdd(&g_cntr[src[e]], 1);
}

__global__ void scan_kernel() {
    const int* cnt = blockIdx.x ? g_cntr : g_cntf;
    int* off       = blockIdx.x ? g_offr : g_offf;
    __shared__ int wsum[32];
    __shared__ int chunk_total;
    __shared__ int carry;
    int tid = threadIdx.x, lane = tid & 31, wid = tid >> 5;
    if (tid == 0) carry = 0;
    __syncthreads();
    for (int base = 0; base < NN; base += 1024) {
        int i = base + tid;
        int v = (i < NN) ? cnt[i] : 0;
        int x = v;
        #pragma unroll
        for (int d = 1; d < 32; d <<= 1) {
            int t = __shfl_up_sync(0xffffffffu, x, d);
            if (lane >= d) x += t;
        }
        if (lane == 31) wsum[wid] = x;
        __syncthreads();
        if (wid == 0) {
            int wv = wsum[lane];
            int y = wv;
            #pragma unroll
            for (int d = 1; d < 32; d <<= 1) {
                int t = __shfl_up_sync(0xffffffffu, y, d);
                if (lane >= d) y += t;
            }
            if (lane == 31) chunk_total = y;
            wsum[lane] = y - wv;
        }
        __syncthreads();
        if (i < NN) off[i] = carry + wsum[wid] + (x - v);
        __syncthreads();
        if (tid == 0) carry += chunk_total;
        __syncthreads();
    }
    if (threadIdx.x == 0) off[NN] = carry;
}

__global__ void invcur_kernel() {
    int i = blockIdx.x * blockDim.x + threadIdx.x;
    if (i >= NN) return;
    g_invf[i] = 1.f / fmaxf((float)g_cntf[i], 1.f);
    g_invr[i] = 1.f / fmaxf((float)g_cntr[i], 1.f);
    g_curf[i] = g_offf[i];
    g_curr[i] = g_offr[i];
}

__global__ void fill_kernel(const int* __restrict__ src, const int* __restrict__ tgt) {
    int e = blockIdx.x * blockDim.x + threadIdx.x;
    if (e >= EE) return;
    int s = src[e], t = tgt[e];
    g_csrf[atomicAdd(&g_curf[t], 1)] = s;
    g_csrr[atomicAdd(&g_curr[s], 1)] = t;
}

// ---------------- merged weight prep (single fp16 plane) ----------------
__global__ void prep_w(const float* __restrict__ preW,
                       const float* __restrict__ cwl, const float* __restrict__ cwr,
                       const float* __restrict__ rwl, const float* __restrict__ rwr) {
    int idx = blockIdx.x * blockDim.x + threadIdx.x;
    if (idx < 256 * KB) {
        int n = idx / KB, k = idx % KB;
        float v = (k < 223) ? preW[(size_t)k * 256 + n] : 0.f;
        g_wbase[idx] = __float2half_rn(v);
        return;
    }
    idx -= 256 * KB;
    if (idx < 256 * KS) {
        int n = idx / KS, k = idx % KS;
        float v = (k < 42) ? preW[(size_t)(223 + k) * 256 + n] : 0.f;
        g_wsamp[idx] = __float2half_rn(v);
        return;
    }
    int j = idx - 256 * KS;
    if (j >= NL * 512 * 256) return;
    int l = j >> 17;
    int r2 = j & 131071;
    int n = r2 >> 8, k = r2 & 255;
    int mat = n >> 7, o = n & 127;
    const float* s = (mat == 0) ? cwl : (mat == 1) ? cwr : (mat == 2) ? rwl : rwr;
    float v = s[(size_t)l * 32768 + k * 128 + o];
    g_wlay[(size_t)l * (512 * 256) + (size_t)n * 256 + k] = __float2half_rn(v);
}

// ---------------- merged input assembly ----------------
__global__ void assemble_kernel(const float* __restrict__ xf, const float* __restrict__ dimf,
                                const float* __restrict__ layf, const float* __restrict__ tilef,
                                const float* __restrict__ emb, const int* __restrict__ opc,
                                const int* __restrict__ batch) {
    size_t idx = (size_t)blockIdx.x * blockDim.x + threadIdx.x;
    const size_t baseTot = (size_t)NBPAD * KB;
    if (idx < baseTot) {
        int c = (int)(idx % KB);
        int n = (int)(idx / KB);
        float v = 0.f;
        if (n < NN) {
            if (c < 53)       v = xf[(size_t)n * 53 + c];
            else if (c < 85)  v = emb[(size_t)opc[n] * 32 + (c - 53)];
            else if (c < 223) v = dimf[(size_t)n * 138 + (c - 85)];
        }
        g_xinb[idx] = __float2half_rn(v);
        return;
    }
    idx -= baseTot;
    if (idx >= (size_t)MPAD * KS) return;
    int c = (int)(idx % KS);
    int m = (int)(idx / KS);
    float v = 0.f;
    if (m < MROWS) {
        int s = m / NN, n = m % NN;
        if (c < 24)      v = layf[((size_t)n * SAMP + s) * 24 + c];
        else if (c < 42) v = tilef[((size_t)batch[n] * SAMP + s) * 18 + (c - 24)];
    }
    g_xins[idx] = __float2half_rn(v);
}

// ---------------- fp16 single-pass streaming GEMM, CTA 256x64, warp 64x32 ----------------
constexpr int STAGE = 25600;
constexpr int NSTG  = 3;
constexpr int GEMM_SMEM = NSTG * STAGE;   // 76800

__global__ __launch_bounds__(256, 2) void gemm_mma(
    const __half* __restrict__ A, int lda, int kchunks,
    const __half* __restrict__ W, int kw,
    const float* __restrict__ bias, const __half* __restrict__ Y0, int mode,
    __half* __restrict__ O, int ldc) {
    extern __shared__ char smem[];
    uint32_t sb = smem_u32(smem);
    const int tid = threadIdx.x;
    const int lane = tid & 31, wid = tid >> 5;
    const int wm = wid >> 1, wn = wid & 1;
    const size_t m0 = (size_t)blockIdx.y * 256;
    const int n0 = blockIdx.x * 64;

    const __half* srcb[5];
    uint32_t dsto[5];
    #pragma unroll
    for (int i = 0; i < 5; i++) {
        if (i < 4) {
            int u = tid + i * 256;
            int row = u >> 2, seg = u & 3;
            srcb[i] = A + (m0 + row) * (size_t)lda + seg * 8;
            dsto[i] = (uint32_t)(row * 80 + seg * 16);
        } else {
            int col = tid >> 2, sg = tid & 3;
            srcb[i] = W + (size_t)(n0 + col) * kw + sg * 8;
            dsto[i] = (uint32_t)(20480 + col * 80 + sg * 16);
        }
    }

    float acc[4][4][4];
    #pragma unroll
    for (int i = 0; i < 4; i++)
        #pragma unroll
        for (int j = 0; j < 4; j++)
            #pragma unroll
            for (int q = 0; q < 4; q++) acc[i][j][q] = 0.f;

    #pragma unroll
    for (int i = 0; i < 5; i++) cp16(sb + dsto[i], srcb[i]);
    cp_commit();
    if (kchunks > 1) {
        #pragma unroll
        for (int i = 0; i < 5; i++) cp16(sb + STAGE + dsto[i], srcb[i] + 32);
        cp_commit();
    }
    cp_wait1();
    __syncthreads();

    const int sub = lane >> 3, rr = lane & 7;
    const int ro = (sub & 1) * 8 + rr;
    const int co = ((sub >> 1) & 1) * 8;

    for (int ch = 0; ch < kchunks; ch++) {
        if (ch + 2 < kchunks) {
            uint32_t db = sb + ((ch + 2) % NSTG) * STAGE;
            int koff = (ch + 2) * 32;
            #pragma unroll
            for (int i = 0; i < 5; i++) cp16(db + dsto[i], srcb[i] + koff);
            cp_commit();
        }
        uint32_t base = sb + (ch % NSTG) * STAGE;
        #pragma unroll
        for (int kk = 0; kk < 32; kk += 16) {
            uint32_t af[4][4];
            #pragma unroll
            for (int mi = 0; mi < 4; mi++)
                ldsm4(af[mi], base + (uint32_t)((wm * 64 + mi * 16 + ro) * 80 + (kk + co) * 2));
            uint32_t bfr[4][2];
            #pragma unroll
            for (int j2 = 0; j2 < 2; j2++) {
                uint32_t t4[4];
                ldsm4(t4, base + 20480 +
                      (uint32_t)((wn * 32 + j2 * 16 + ro) * 80 + (kk + co) * 2));
                bfr[2 * j2][0] = t4[0]; bfr[2 * j2][1] = t4[2];
                bfr[2 * j2 + 1][0] = t4[1]; bfr[2 * j2 + 1][1] = t4[3];
            }
            #pragma unroll
            for (int mi = 0; mi < 4; mi++)
                #pragma unroll
                for (int nj = 0; nj < 4; nj++)
                    mma16816(acc[mi][nj], af[mi], bfr[nj]);
        }
        if (ch + 1 < kchunks) {
            if (ch + 2 < kchunks) cp_wait1(); else cp_wait0();
            __syncthreads();
        }
    }

    const int g = lane >> 2, t4i = lane & 3;
    #pragma unroll
    for (int mi = 0; mi < 4; mi++) {
        #pragma unroll
        for (int nj = 0; nj < 4; nj++) {
            size_t row = m0 + wm * 64 + mi * 16 + g;
            int col = n0 + wn * 32 + nj * 8 + t4i * 2;
            float2 v0 = make_float2(acc[mi][nj][0], acc[mi][nj][1]);
            float2 v1 = make_float2(acc[mi][nj][2], acc[mi][nj][3]);
            if (mode == 1) {
                size_t nd0 = row < (size_t)NN ? row : (row < (size_t)MROWS ? row - NN : 0);
                size_t row8 = row + 8;
                size_t nd1 = row8 < (size_t)NN ? row8 : (row8 < (size_t)MROWS ? row8 - NN : 0);
                float2 y0 = __half22float2(*reinterpret_cast<const __half2*>(Y0 + nd0 * 256 + col));
                float2 y1 = __half22float2(*reinterpret_cast<const __half2*>(Y0 + nd1 * 256 + col));
                float b0v = bias[col], b1v = bias[col + 1];
                v0.x = fmaxf(v0.x + y0.x + b0v, 0.f); v0.y = fmaxf(v0.y + y0.y + b1v, 0.f);
                v1.x = fmaxf(v1.x + y1.x + b0v, 0.f); v1.y = fmaxf(v1.y + y1.y + b1v, 0.f);
            }
            *reinterpret_cast<__half2*>(O + row * ldc + col) = __float22half2_rn(v0);
            *reinterpret_cast<__half2*>(O + (row + 8) * ldc + col) = __float22half2_rn(v1);
        }
    }
}

// ---------------- gather helpers ----------------
__device__ __forceinline__ void acc4h(float* a, uint2 u) {
    float2 f0 = __half22float2(*reinterpret_cast<const __half2*>(&u.x));
    float2 f1 = __half22float2(*reinterpret_cast<const __half2*>(&u.y));
    a[0] += f0.x; a[1] += f0.y; a[2] += f1.x; a[3] += f1.y;
}
__device__ __forceinline__ void store4_h(__half* X, size_t off, const float* v) {
    __half2 p0 = __float22half2_rn(make_float2(v[0], v[1]));
    __half2 p1 = __float22half2_rn(make_float2(v[2], v[3]));
    uint2 u;
    u.x = *reinterpret_cast<uint32_t*>(&p0);
    u.y = *reinterpret_cast<uint32_t*>(&p1);
    *reinterpret_cast<uint2*>(X + off) = u;
}

// ---------------- plain gather (layers 0,1) — exact R12 kernel ----------------
__global__ void gather_ep(const __half* __restrict__ P,
                          const float* __restrict__ bconv, const float* __restrict__ brev,
                          __half* __restrict__ X) {
    int w = (blockIdx.x * blockDim.x + threadIdx.x) >> 5;
    int lane = threadIdx.x & 31;
    if (w >= NN) return;
    int c4 = lane * 4;
    float aF0[4] = {0, 0, 0, 0}, aF1[4] = {0, 0, 0, 0};
    float aR0[4] = {0, 0, 0, 0}, aR1[4] = {0, 0, 0, 0};
    int b0 = g_offf[w], b1 = g_offf[w + 1];
    for (int j = b0; j < b1; j++) {
        int nb = g_csrf[j];
        acc4h(aF0, *reinterpret_cast<const uint2*>(P + (size_t)nb * 512 + c4));
        acc4h(aF1, *reinterpret_cast<const uint2*>(P + (size_t)(NN + nb) * 512 + c4));
    }
    b0 = g_offr[w]; b1 = g_offr[w + 1];
    for (int j = b0; j < b1; j++) {
        int nb = g_csrr[j];
        acc4h(aR0, *reinterpret_cast<const uint2*>(P + (size_t)nb * 512 + 256 + c4));
        acc4h(aR1, *reinterpret_cast<const uint2*>(P + (size_t)(NN + nb) * 512 + 256 + c4));
    }
    float ivf = g_invf[w], ivr = g_invr[w];
    float4 bc = *reinterpret_cast<const float4*>(bconv + c4);
    float4 br = *reinterpret_cast<const float4*>(brev + c4);
    const float* bcp = &bc.x;
    const float* brp = &br.x;
    #pragma unroll
    for (int s = 0; s < SAMP; s++) {
        size_t rowm = (size_t)s * NN + w;
        const float* aF = s ? aF1 : aF0;
        const float* aR = s ? aR1 : aR0;
        float rf[4] = {0, 0, 0, 0}, rr2[4] = {0, 0, 0, 0};
        acc4h(rf,  *reinterpret_cast<const uint2*>(P + rowm * 512 + 128 + c4));
        acc4h(rr2, *reinterpret_cast<const uint2*>(P + rowm * 512 + 384 + c4));
        float oF[4], oR[4];
        #pragma unroll
        for (int q = 0; q < 4; q++) {
            oF[q] = fmaxf(aF[q] * ivf + rf[q]  + bcp[q], 0.f);
            oR[q] = fmaxf(aR[q] * ivr + rr2[q] + brp[q], 0.f);
        }
        store4_h(X, rowm * MIDC + c4, oF);
        store4_h(X, rowm * MIDC + 128 + c4, oR);
    }
}

// ---------------- head-fused gather (layers 2,3); grid exactly NN*32/256 ----------------
template <bool WRITEX>
__global__ void gather_head(const __half* __restrict__ P,
                            const float* __restrict__ bconv, const float* __restrict__ brev,
                            __half* __restrict__ X,
                            const float* __restrict__ hw,
                            const int* __restrict__ batchv, float* __restrict__ out) {
    __shared__ float part[GG * SAMP];
    int tid = threadIdx.x;
    if (tid < GG * SAMP) part[tid] = 0.f;
    __syncthreads();
    int w = (blockIdx.x * blockDim.x + tid) >> 5;
    int lane = tid & 31;
    int c4 = lane * 4;
    float aF0[4] = {0, 0, 0, 0}, aF1[4] = {0, 0, 0, 0};
    float aR0[4] = {0, 0, 0, 0}, aR1[4] = {0, 0, 0, 0};
    int b0 = g_offf[w], b1 = g_offf[w + 1];
    for (int j = b0; j < b1; j++) {
        int nb = g_csrf[j];
        acc4h(aF0, *reinterpret_cast<const uint2*>(P + (size_t)nb * 512 + c4));
        acc4h(aF1, *reinterpret_cast<const uint2*>(P + (size_t)(NN + nb) * 512 + c4));
    }
    b0 = g_offr[w]; b1 = g_offr[w + 1];
    for (int j = b0; j < b1; j++) {
        int nb = g_csrr[j];
        acc4h(aR0, *reinterpret_cast<const uint2*>(P + (size_t)nb * 512 + 256 + c4));
        acc4h(aR1, *reinterpret_cast<const uint2*>(P + (size_t)(NN + nb) * 512 + 256 + c4));
    }
    float ivf = g_invf[w], ivr = g_invr[w];
    float4 bc = *reinterpret_cast<const float4*>(bconv + c4);
    float4 br = *reinterpret_cast<const float4*>(brev + c4);
    const float* bcp = &bc.x;
    const float* brp = &br.x;
    float hwc[4], hwr[4];
    #pragma unroll
    for (int q = 0; q < 4; q++) {
        hwc[q] = hw[c4 + q];
        hwr[q] = hw[128 + c4 + q];
    }
    float dot[SAMP];
    #pragma unroll
    for (int s = 0; s < SAMP; s++) {
        size_t rowm = (size_t)s * NN + w;
        const float* aF = s ? aF1 : aF0;
        const float* aR = s ? aR1 : aR0;
        float rf[4] = {0, 0, 0, 0}, rr2[4] = {0, 0, 0, 0};
        acc4h(rf,  *reinterpret_cast<const uint2*>(P + rowm * 512 + 128 + c4));
        acc4h(rr2, *reinterpret_cast<const uint2*>(P + rowm * 512 + 384 + c4));
        float oF[4], oR[4];
        #pragma unroll
        for (int q = 0; q < 4; q++) {
            oF[q] = fmaxf(aF[q] * ivf + rf[q]  + bcp[q], 0.f);
            oR[q] = fmaxf(aR[q] * ivr + rr2[q] + brp[q], 0.f);
        }
        if (WRITEX) {
            store4_h(X, rowm * MIDC + c4, oF);
            store4_h(X, rowm * MIDC + 128 + c4, oR);
        }
        float d = 0.f;
        #pragma unroll
        for (int q = 0; q < 4; q++) d += oF[q] * hwc[q] + oR[q] * hwr[q];
        dot[s] = d;
    }
    #pragma unroll
    for (int s = 0; s < SAMP; s++)
        #pragma unroll
        for (int d = 16; d > 0; d >>= 1)
            dot[s] += __shfl_down_sync(0xffffffffu, dot[s], d);
    if (lane == 0) {
        int g = batchv[w];
        atomicAdd(&part[g * SAMP + 0], dot[0]);
        atomicAdd(&part[g * SAMP + 1], dot[1]);
    }
    __syncthreads();
    if (tid < GG * SAMP && part[tid] != 0.f) atomicAdd(&out[tid], part[tid]);
}

// ---------------- output init ----------------
__global__ void init_out_kernel(float* out, const float* __restrict__ hb) {
    int i = threadIdx.x;
    if (i < GG * SAMP) out[i] = hb[0];
}

// ---------------- launch ----------------
extern "C" void kernel_launch(void* const* d_in, const int* in_sizes, int n_in,
                              void* d_out, int out_size) {
    const float* x_feat    = (const float*)d_in[0];
    const float* dim_feat  = (const float*)d_in[1];
    const float* lay_feat  = (const float*)d_in[2];
    const float* tile_feat = (const float*)d_in[3];
    const float* emb       = (const float*)d_in[4];
    const float* preW      = (const float*)d_in[5];
    const float* preb      = (const float*)d_in[6];
    const float* convWl    = (const float*)d_in[7];
    const float* convWr    = (const float*)d_in[8];
    const float* convb     = (const float*)d_in[9];
    const float* revWl     = (const float*)d_in[10];
    const float* revWr     = (const float*)d_in[11];
    const float* revb      = (const float*)d_in[12];
    const float* headW     = (const float*)d_in[13];
    const float* headb     = (const float*)d_in[14];
    const int*   opcode    = (const int*)d_in[15];
    const int*   batch     = (const int*)d_in[16];
    const int*   eidx      = (const int*)d_in[17];
    const int* src = eidx;
    const int* tgt = eidx + EE;
    float* out = (float*)d_out;

    int *cntf, *cntr;
    __half *xinb, *xins, *y0, *xa, *xb, *P, *wbase, *wsamp, *wlay;
    cudaGetSymbolAddress((void**)&cntf, g_cntf);
    cudaGetSymbolAddress((void**)&cntr, g_cntr);
    cudaGetSymbolAddress((void**)&xinb, g_xinb);
    cudaGetSymbolAddress((void**)&xins, g_xins);
    cudaGetSymbolAddress((void**)&y0, g_y0);
    cudaGetSymbolAddress((void**)&xa, g_xa);
    cudaGetSymbolAddress((void**)&xb, g_xb);
    cudaGetSymbolAddress((void**)&P, g_P);
    cudaGetSymbolAddress((void**)&wbase, g_wbase);
    cudaGetSymbolAddress((void**)&wsamp, g_wsamp);
    cudaGetSymbolAddress((void**)&wlay, g_wlay);

    static bool attr_done = false;
    if (!attr_done) {
        cudaFuncSetAttribute(gemm_mma, cudaFuncAttributeMaxDynamicSharedMemorySize, GEMM_SMEM);
        attr_done = true;
    }

    cudaMemsetAsync(cntf, 0, NN * sizeof(int), 0);                                    // 1
    cudaMemsetAsync(cntr, 0, NN * sizeof(int), 0);                                    // 2
    {
        int tot = 256 * KB + 256 * KS + NL * 512 * 256;
        prep_w<<<(tot + 255) / 256, 256>>>(preW, convWl, convWr, revWl, revWr);       // 3
    }
    {
        size_t tot = (size_t)NBPAD * KB + (size_t)MPAD * KS;
        assemble_kernel<<<(unsigned)((tot + 255) / 256), 256>>>(                      // 4
            x_feat, dim_feat, lay_feat, tile_feat, emb, opcode, batch);
    }
    {
        dim3 grid(4, MTB);                                                            // 5: base GEMM
        gemm_mma<<<grid, 256, GEMM_SMEM>>>(xinb, KB, KB / 32, wbase, KB,
                                           nullptr, nullptr, 0, y0, 256);
    }
    {
        dim3 grid(4, MT256);                                                          // 6: sample GEMM (ncu slot)
        gemm_mma<<<grid, 256, GEMM_SMEM>>>(xins, KS, KS / 32, wsamp, KS,
                                           preb, y0, 1, xa, 256);
    }
    // graph structure (needed before first gather)
    hist_kernel<<<(EE + 255) / 256, 256>>>(src, tgt);
    scan_kernel<<<2, 1024>>>();
    invcur_kernel<<<(NN + 255) / 256, 256>>>();
    fill_kernel<<<(EE + 255) / 256, 256>>>(src, tgt);
    init_out_kernel<<<1, 32>>>(out, headb);

    __half *cur = xa, *nxt = xb;
    for (int i = 0; i < NL; i++) {
        dim3 grid(8, MT256);
        gemm_mma<<<grid, 256, GEMM_SMEM>>>(cur, 256, 8,
                                           wlay + (size_t)i * (512 * 256), 256,
                                           nullptr, nullptr, 0, P, 512);
        if (i < 2) {
            gather_ep<<<NN * 32 / 256, 256>>>(P, convb + i * 128, revb + i * 128, nxt);
        } else if (i == 2) {
            gather_head<true><<<NN * 32 / 256, 256>>>(P, convb + i * 128, revb + i * 128,
                                                      nxt, headW, batch, out);
        } else {
            gather_head<false><<<NN * 32 / 256, 256>>>(P, convb + i * 128, revb + i * 128,
                                                       nullptr, headW + 256, batch, out);
        }
        __half* t = cur; cur = nxt; nxt = t;
    }
}